// round 8
// baseline (speedup 1.0000x reference)
#include <cuda_runtime.h>
#include <cuda_bf16.h>
#include <mma.h>
#include <math.h>

#define NN 50000
#define EE 800000
#define ET (EE + NN)     // edges + self loops
#define HID 128
#define SLOPE 0.2f
#define LN_EPS 1e-5f
#define SCAN_NB 13       // ceil(50000/4096)
#define WGEMM_NB 782     // ceil(50000/64)
#define HIST_NB 1563     // ceil(200000/128)

typedef unsigned long long ull;
using namespace nvcuda;

// ---------------- scratch (device globals; no allocation allowed) ----------
__device__ int   g_deg[NN];          // zero at start of every run (self-restoring)
__device__ int   g_rowptr[NN + 1];
__device__ int   g_cursor[NN];
__device__ int   g_blocksums[64];
__device__ int   g_src[ET];
__device__ float g_xl[NN * HID];
__device__ float g_xr[NN * HID];
__device__ float g_h1[NN * HID];

// ---------------- f32x2 packed math helpers --------------------------------
__device__ __forceinline__ ull pk2(float x) {
    ull r; asm("mov.b64 %0, {%1, %1};" : "=l"(r) : "f"(x)); return r;
}
__device__ __forceinline__ ull mk2(float lo, float hi) {
    ull r; asm("mov.b64 %0, {%1, %2};" : "=l"(r) : "f"(lo), "f"(hi)); return r;
}
__device__ __forceinline__ void fma2(ull& d, ull a, ull b) {
    asm("fma.rn.f32x2 %0, %1, %2, %0;" : "+l"(d) : "l"(a), "l"(b));
}
__device__ __forceinline__ ull fma2v(ull a, ull b, ull c) {
    ull r; asm("fma.rn.f32x2 %0, %1, %2, %3;" : "=l"(r) : "l"(a), "l"(b), "l"(c)); return r;
}
__device__ __forceinline__ ull add2v(ull a, ull b) {
    ull r; asm("add.rn.f32x2 %0, %1, %2;" : "=l"(r) : "l"(a), "l"(b)); return r;
}
__device__ __forceinline__ ull mul2v(ull a, ull b) {
    ull r; asm("mul.rn.f32x2 %0, %1, %2;" : "=l"(r) : "l"(a), "l"(b)); return r;
}
__device__ __forceinline__ float2 up2(ull v) {
    float2 f; asm("mov.b64 {%0, %1}, %2;" : "=f"(f.x), "=f"(f.y) : "l"(v)); return f;
}
#define ABS2MASK 0x7FFFFFFF7FFFFFFFull

// ---------------- tensor-core GEMM: Y[M,128] = X[M,K] @ W[K,128] -----------
// TF32 wmma (m16n16k8) with 3-MMA error compensation:
//   x = hi + lo (both tf32);  x*w ~= hi*wh + hi*wl + lo*wh  (err ~2^-22)
// Block: 128 threads = 4 warps; tile M=64, N=128; warp = 16 rows x 128 cols.
// K staged in 16-wide chunks, pre-split hi/lo in smem (24KB).
template <int K>
__device__ __forceinline__ void wgemm_body(const float* __restrict__ X,
                                           const float* __restrict__ W,
                                           float* __restrict__ Y,
                                           int M, int bx) {
    __shared__ float Xh[64][16], Xl[64][16];
    __shared__ float Wh[16][128], Wl[16][128];

    int tid = threadIdx.x;
    int warp = tid >> 5;
    int rowBase = bx * 64;

    wmma::fragment<wmma::accumulator, 16, 16, 8, float> acc[8];
#pragma unroll
    for (int n = 0; n < 8; n++) wmma::fill_fragment(acc[n], 0.0f);

    for (int kc = 0; kc < K; kc += 16) {
        // stage X chunk 64x16, split hi/lo
#pragma unroll
        for (int it = 0; it < 8; it++) {
            int i = tid + it * 128;        // 0..1023
            int r = i >> 4, c = i & 15;
            int gr = rowBase + r;
            float v = (gr < M) ? X[(size_t)gr * K + kc + c] : 0.0f;
            float h = wmma::__float_to_tf32(v);
            Xh[r][c] = h;
            Xl[r][c] = wmma::__float_to_tf32(v - h);
        }
        // stage W chunk 16x128, split hi/lo
#pragma unroll
        for (int it = 0; it < 16; it++) {
            int i = tid + it * 128;        // 0..2047
            int r = i >> 7, c = i & 127;
            float v = W[(size_t)(kc + r) * HID + c];
            float h = wmma::__float_to_tf32(v);
            Wh[r][c] = h;
            Wl[r][c] = wmma::__float_to_tf32(v - h);
        }
        __syncthreads();

#pragma unroll
        for (int ks = 0; ks < 16; ks += 8) {
            wmma::fragment<wmma::matrix_a, 16, 16, 8, wmma::precision::tf32,
                           wmma::row_major> ah, al;
            wmma::load_matrix_sync(ah, &Xh[warp * 16][ks], 16);
            wmma::load_matrix_sync(al, &Xl[warp * 16][ks], 16);
#pragma unroll
            for (int n = 0; n < 8; n++) {
                wmma::fragment<wmma::matrix_b, 16, 16, 8, wmma::precision::tf32,
                               wmma::row_major> bh, bl;
                wmma::load_matrix_sync(bh, &Wh[ks][n * 16], 128);
                wmma::load_matrix_sync(bl, &Wl[ks][n * 16], 128);
                wmma::mma_sync(acc[n], ah, bh, acc[n]);
                wmma::mma_sync(acc[n], ah, bl, acc[n]);
                wmma::mma_sync(acc[n], al, bh, acc[n]);
            }
        }
        __syncthreads();
    }

    int row = rowBase + warp * 16;
    if (row < M) {    // M % 16 == 0 -> warp tiles are fully valid or invalid
#pragma unroll
        for (int n = 0; n < 8; n++)
            wmma::store_matrix_sync(&Y[(size_t)row * HID + n * 16], acc[n],
                                    HID, wmma::mem_row_major);
    }
}

// ---------------- fused: layer-1 dual GEMM + degree histogram --------------
__global__ void __launch_bounds__(128)
gemm1_hist_kernel(const float* __restrict__ X,
                  const float* __restrict__ WA, const float* __restrict__ WB,
                  float* __restrict__ YA, float* __restrict__ YB,
                  const int* __restrict__ ei, int M) {
    if (blockIdx.x < 2 * WGEMM_NB) {
        int sel = blockIdx.x >= WGEMM_NB;
        wgemm_body<32>(X, sel ? WB : WA, sel ? YB : YA, M,
                       blockIdx.x - sel * WGEMM_NB);
    } else {
        int e4 = (blockIdx.x - 2 * WGEMM_NB) * 128 + threadIdx.x;
        if (e4 < EE / 4) {
            int4 d = ((const int4*)(ei + EE))[e4];
            atomicAdd(&g_deg[d.x], 1);
            atomicAdd(&g_deg[d.y], 1);
            atomicAdd(&g_deg[d.z], 1);
            atomicAdd(&g_deg[d.w], 1);
        }
    }
}

__global__ void __launch_bounds__(128)
gemm_dual_kernel(const float* __restrict__ X,
                 const float* __restrict__ WA, const float* __restrict__ WB,
                 float* __restrict__ YA, float* __restrict__ YB, int M) {
    wgemm_body<128>(X, blockIdx.y ? WB : WA, blockIdx.y ? YB : YA, M, blockIdx.x);
}

// ---------------- CSR scan + scatter (R4-proven multi-block) ----------------
__global__ void scan1_kernel() {
    __shared__ int sh[1024];
    int t = threadIdx.x;
    int base = blockIdx.x * 4096 + t * 4;
    // +1 = implicit self loop per node
    int v0 = (base + 0 < NN) ? g_deg[base + 0] + 1 : 0;
    int v1 = (base + 1 < NN) ? g_deg[base + 1] + 1 : 0;
    int v2 = (base + 2 < NN) ? g_deg[base + 2] + 1 : 0;
    int v3 = (base + 3 < NN) ? g_deg[base + 3] + 1 : 0;
    int p0 = v0, p1 = p0 + v1, p2 = p1 + v2, p3 = p2 + v3;
    sh[t] = p3;
    __syncthreads();
    for (int off = 1; off < 1024; off <<= 1) {
        int add = (t >= off) ? sh[t - off] : 0;
        __syncthreads();
        sh[t] += add;
        __syncthreads();
    }
    int excl = sh[t] - p3;
    if (base + 0 < NN) g_rowptr[base + 0] = excl;
    if (base + 1 < NN) g_rowptr[base + 1] = excl + p0;
    if (base + 2 < NN) g_rowptr[base + 2] = excl + p1;
    if (base + 3 < NN) g_rowptr[base + 3] = excl + p2;
    if (t == 1023) g_blocksums[blockIdx.x] = sh[1023];  // raw block totals
}

__global__ void scan3_kernel() {
    int i = blockIdx.x * blockDim.x + threadIdx.x;
    if (i < NN) {
        int idx = i >> 12;
        int off = 0;
        for (int b = 0; b < idx; b++) off += g_blocksums[b];
        int r = g_rowptr[i] + off;
        g_rowptr[i] = r;
        g_cursor[i] = r;
        g_deg[i] = 0;               // restore for next graph replay
    } else if (i == NN) {
        g_rowptr[NN] = ET;
    }
}

__global__ void scatter_kernel(const int* __restrict__ ei) {
    int i = blockIdx.x * blockDim.x + threadIdx.x;
    if (i >= ET) return;
    int s, d;
    if (i < EE) { s = ei[i]; d = ei[EE + i]; }
    else        { s = i - EE; d = s; }
    int p = atomicAdd(&g_cursor[d], 1);
    g_src[p] = s;
}

// ---------------- GATv2 aggregation core (R7-proven) ------------------------
// packed f32x2 math + unroll-4 reload-in-place pipeline.
// Logits tiny (weights ~0.05) -> exp without max-shift is safe.
// leaky_relu(t) = 0.6t + 0.4|t| for slope 0.2.
__device__ __forceinline__ float4 agg_core(int node, int lane,
                                           const float* __restrict__ xl,
                                           const float* __restrict__ xr,
                                           const float* __restrict__ att) {
    float4 xr4 = *(const float4*)&xr[(size_t)node * HID + lane * 4];
    float4 a4  = *(const float4*)&att[lane * 4];
    const float c6 = 0.5f * (1.f + SLOPE), c4 = 0.5f * (1.f - SLOPE);
    ull xrA = mk2(xr4.x, xr4.y), xrB = mk2(xr4.z, xr4.w);
    ull a06A = mk2(a4.x * c6, a4.y * c6), a06B = mk2(a4.z * c6, a4.w * c6);
    ull a04A = mk2(a4.x * c4, a4.y * c4), a04B = mk2(a4.z * c4, a4.w * c4);

    int e0 = g_rowptr[node], e1 = g_rowptr[node + 1];

    ull accA = 0ull, accB = 0ull;      // bit pattern == {0.f,0.f}
    float denom = 0.f;

#define LOADE(k, dA, dB) {                                                    \
        int _s = __shfl_sync(0xffffffffu, sReg, (k));                         \
        ulonglong2 _v = *(const ulonglong2*)&xl[(size_t)_s * HID + lane * 4]; \
        dA = _v.x; dB = _v.y; }

#define PROCE(cA, cB) {                                                       \
        ull t01 = add2v(cA, xrA), t23 = add2v(cB, xrB);                       \
        ull v2 = mul2v(t01, a06A);                                            \
        v2 = fma2v(t01 & ABS2MASK, a04A, v2);                                 \
        v2 = fma2v(t23, a06B, v2);                                            \
        v2 = fma2v(t23 & ABS2MASK, a04B, v2);                                 \
        float2 vv = up2(v2);                                                  \
        float v = vv.x + vv.y;                                                \
        v += __shfl_xor_sync(0xffffffffu, v, 1);                              \
        v += __shfl_xor_sync(0xffffffffu, v, 2);                              \
        v += __shfl_xor_sync(0xffffffffu, v, 4);                              \
        float e = __expf(v);                                                  \
        denom += e;                                                           \
        ull ep = pk2(e);                                                      \
        fma2(accA, ep, cA);                                                   \
        fma2(accB, ep, cB); }

    for (int eb = e0; eb < e1; eb += 32) {
        int cnt = min(32, e1 - eb);
        // invalid lanes get node 0 (safe to load, never processed)
        int sReg = (lane < cnt) ? g_src[eb + lane] : 0;

        ull c0a, c0b, c1a, c1b, c2a, c2b, c3a, c3b;
        LOADE(0, c0a, c0b);
        LOADE(1, c1a, c1b);
        LOADE(2, c2a, c2b);
        LOADE(3, c3a, c3b);

        int j = 0;
        for (; j + 4 <= cnt; j += 4) {
            PROCE(c0a, c0b); LOADE(j + 4, c0a, c0b);
            PROCE(c1a, c1b); LOADE(j + 5, c1a, c1b);
            PROCE(c2a, c2b); LOADE(j + 6, c2a, c2b);
            PROCE(c3a, c3b); LOADE(j + 7, c3a, c3b);
        }
        int rem = cnt - j;           // 0..3, warp-uniform
        if (rem > 0) { PROCE(c0a, c0b); }
        if (rem > 1) { PROCE(c1a, c1b); }
        if (rem > 2) { PROCE(c2a, c2b); }
    }
#undef LOADE
#undef PROCE

    float inv = 1.f / denom;
    float2 rA = up2(accA), rB = up2(accB);
    float4 res;
    res.x = rA.x * inv; res.y = rA.y * inv;
    res.z = rB.x * inv; res.w = rB.y * inv;
    return res;
}

__device__ __forceinline__ float4 ln_epi(float4 r, int lane,
                                         const float* __restrict__ bias,
                                         const float* __restrict__ gamma,
                                         const float* __restrict__ beta) {
    float4 b4 = *(const float4*)&bias[lane * 4];
    r.x += b4.x; r.y += b4.y; r.z += b4.z; r.w += b4.w;
    float s1 = r.x + r.y + r.z + r.w;
    float s2 = r.x * r.x + r.y * r.y + r.z * r.z + r.w * r.w;
#pragma unroll
    for (int off = 16; off > 0; off >>= 1) {
        s1 += __shfl_xor_sync(0xffffffffu, s1, off);
        s2 += __shfl_xor_sync(0xffffffffu, s2, off);
    }
    float mean = s1 * (1.f / 128.f);
    float var  = s2 * (1.f / 128.f) - mean * mean;
    float rstd = rsqrtf(var + LN_EPS);
    float4 g4 = *(const float4*)&gamma[lane * 4];
    float4 bb4 = *(const float4*)&beta[lane * 4];
    r.x = (r.x - mean) * rstd * g4.x + bb4.x;
    r.y = (r.y - mean) * rstd * g4.y + bb4.y;
    r.z = (r.z - mean) * rstd * g4.z + bb4.z;
    r.w = (r.w - mean) * rstd * g4.w + bb4.w;
    return r;
}

// ---------------- layer 1: agg + bias + LN + ELU -> h1 ---------------------
__global__ void __launch_bounds__(256)
gat_layer1_kernel(const float* __restrict__ xl, const float* __restrict__ xr,
                  const float* __restrict__ att, const float* __restrict__ bias,
                  const float* __restrict__ gamma, const float* __restrict__ beta,
                  float* __restrict__ out, int Nn) {
    int warp = (blockIdx.x * blockDim.x + threadIdx.x) >> 5;
    if (warp >= Nn) return;
    int lane = threadIdx.x & 31;
    float4 r = agg_core(warp, lane, xl, xr, att);
    r = ln_epi(r, lane, bias, gamma, beta);
    r.x = r.x > 0.f ? r.x : expm1f(r.x);
    r.y = r.y > 0.f ? r.y : expm1f(r.y);
    r.z = r.z > 0.f ? r.z : expm1f(r.z);
    r.w = r.w > 0.f ? r.w : expm1f(r.w);
    *(float4*)&out[(size_t)warp * HID + lane * 4] = r;
}

// ---------------- layer 2: agg + bias + LN + residual + ELU + MLP heads ----
__global__ void __launch_bounds__(256)
gat_layer2_heads_kernel(const float* __restrict__ xl, const float* __restrict__ xr,
                        const float* __restrict__ att, const float* __restrict__ bias,
                        const float* __restrict__ gamma, const float* __restrict__ beta,
                        const float* __restrict__ resid,
                        const float* __restrict__ Wp1, const float* __restrict__ bp1,
                        const float* __restrict__ Wp2, const float* __restrict__ bp2,
                        const float* __restrict__ Wu1, const float* __restrict__ bu1,
                        const float* __restrict__ Wu2, const float* __restrict__ bu2,
                        float* __restrict__ out, int Nn) {
    __shared__ float hs[8][128];
    __shared__ float ph[8][64];
    __shared__ float uh[8][32];

    int warp = (blockIdx.x * blockDim.x + threadIdx.x) >> 5;
    if (warp >= Nn) return;
    int lane = threadIdx.x & 31;
    int wid = threadIdx.x >> 5;
    int node = warp;

    float4 r = agg_core(node, lane, xl, xr, att);
    r = ln_epi(r, lane, bias, gamma, beta);
    float4 rs = *(const float4*)&resid[(size_t)node * HID + lane * 4];
    r.x += rs.x; r.y += rs.y; r.z += rs.z; r.w += rs.w;
    r.x = r.x > 0.f ? r.x : expm1f(r.x);
    r.y = r.y > 0.f ? r.y : expm1f(r.y);
    r.z = r.z > 0.f ? r.z : expm1f(r.z);
    r.w = r.w > 0.f ? r.w : expm1f(r.w);

    *(float4*)&hs[wid][lane * 4] = r;
    __syncwarp();

    // hidden layers: pred 64 units (2/lane), unc 32 units (1/lane)
    int u0 = lane * 2;
    float a0 = bp1[u0], a1 = bp1[u0 + 1];
    float b = bu1[lane];
#pragma unroll 8
    for (int k = 0; k < 128; k++) {
        float hk = hs[wid][k];
        float2 w = *(const float2*)&Wp1[(size_t)k * 64 + u0];
        a0 = fmaf(hk, w.x, a0);
        a1 = fmaf(hk, w.y, a1);
        b = fmaf(hk, Wu1[(size_t)k * 32 + lane], b);
    }
    ph[wid][u0]     = fmaxf(a0, 0.f);
    ph[wid][u0 + 1] = fmaxf(a1, 0.f);
    uh[wid][lane]   = fmaxf(b, 0.f);
    __syncwarp();

    if (lane < 6) {
        float o = bp2[lane];
#pragma unroll 8
        for (int u = 0; u < 64; u++) o = fmaf(ph[wid][u], Wp2[u * 6 + lane], o);
        out[(size_t)node * 6 + lane] = o;

        float q = bu2[lane];
#pragma unroll 8
        for (int u = 0; u < 32; u++) q = fmaf(uh[wid][u], Wu2[u * 6 + lane], q);
        out[(size_t)Nn * 6 + (size_t)node * 6 + lane] =
            fmaxf(q, 0.f) + log1pf(__expf(-fabsf(q)));
    }
}

// ---------------- launcher -------------------------------------------------
extern "C" void kernel_launch(void* const* d_in, const int* in_sizes, int n_in,
                              void* d_out, int out_size) {
    const float* x     = (const float*)d_in[0];
    const int*   ei    = (const int*)d_in[1];
    const float* Wl1   = (const float*)d_in[2];
    const float* Wr1   = (const float*)d_in[3];
    const float* att1  = (const float*)d_in[4];
    const float* bias1 = (const float*)d_in[5];
    const float* g1    = (const float*)d_in[6];
    const float* b1    = (const float*)d_in[7];
    const float* Wl2   = (const float*)d_in[8];
    const float* Wr2   = (const float*)d_in[9];
    const float* att2  = (const float*)d_in[10];
    const float* bias2 = (const float*)d_in[11];
    const float* g2    = (const float*)d_in[12];
    const float* b2    = (const float*)d_in[13];
    const float* Wp1   = (const float*)d_in[14];
    const float* bp1   = (const float*)d_in[15];
    const float* Wp2   = (const float*)d_in[16];
    const float* bp2   = (const float*)d_in[17];
    const float* Wu1   = (const float*)d_in[18];
    const float* bu1   = (const float*)d_in[19];
    const float* Wu2   = (const float*)d_in[20];
    const float* bu2   = (const float*)d_in[21];
    float* out = (float*)d_out;

    float *xl, *xr, *h1;
    cudaGetSymbolAddress((void**)&xl, g_xl);
    cudaGetSymbolAddress((void**)&xr, g_xr);
    cudaGetSymbolAddress((void**)&h1, g_h1);

    // fused: layer-1 dual GEMM (tensor cores) + degree histogram
    gemm1_hist_kernel<<<2 * WGEMM_NB + HIST_NB, 128>>>(x, Wl1, Wr1, xl, xr, ei, NN);

    // CSR scan + scatter
    scan1_kernel<<<SCAN_NB, 1024>>>();
    scan3_kernel<<<(NN + 256) / 256, 256>>>();
    scatter_kernel<<<(ET + 255) / 256, 256>>>(ei);

    // layer 1 aggregation
    gat_layer1_kernel<<<(NN + 7) / 8, 256>>>(xl, xr, att1, bias1, g1, b1, h1, NN);

    // layer 2 dual GEMM (tensor cores)
    dim3 ggrid(WGEMM_NB, 2);
    gemm_dual_kernel<<<ggrid, 128>>>(h1, Wl2, Wr2, xl, xr, NN);

    // layer 2 aggregation + heads
    gat_layer2_heads_kernel<<<(NN + 7) / 8, 256>>>(
        xl, xr, att2, bias2, g2, b2, h1,
        Wp1, bp1, Wp2, bp2, Wu1, bu1, Wu2, bu2, out, NN);
}

// round 10
// speedup vs baseline: 1.9444x; 1.9444x over previous
#include <cuda_runtime.h>
#include <cuda_bf16.h>
#include <math.h>

#define NN 50000
#define EE 800000
#define ET (EE + NN)     // edges + self loops
#define HID 128
#define SLOPE 0.2f
#define LN_EPS 1e-5f
#define SCAN_NB 13       // ceil(50000/4096)
#define GEMM_NB 391      // ceil(50000/128)
#define HEADS_NB 782     // ceil(50000/64)

typedef unsigned long long ull;

// ---------------- scratch (device globals; no allocation allowed) ----------
__device__ int   g_deg[NN];          // zero at start of every run (self-restoring)
__device__ int   g_rowptr[NN + 1];
__device__ int   g_cursor[NN];
__device__ int   g_blocksums[64];
__device__ int   g_src[ET];
__device__ float g_xl[NN * HID];
__device__ float g_xr[NN * HID];
__device__ float g_h1[NN * HID];
__device__ float g_h2[NN * HID];

// ---------------- f32x2 packed math helpers --------------------------------
__device__ __forceinline__ ull pk2(float x) {
    ull r; asm("mov.b64 %0, {%1, %1};" : "=l"(r) : "f"(x)); return r;
}
__device__ __forceinline__ ull mk2(float lo, float hi) {
    ull r; asm("mov.b64 %0, {%1, %2};" : "=l"(r) : "f"(lo), "f"(hi)); return r;
}
__device__ __forceinline__ void fma2(ull& d, ull a, ull b) {
    asm("fma.rn.f32x2 %0, %1, %2, %0;" : "+l"(d) : "l"(a), "l"(b));
}
__device__ __forceinline__ ull fma2v(ull a, ull b, ull c) {
    ull r; asm("fma.rn.f32x2 %0, %1, %2, %3;" : "=l"(r) : "l"(a), "l"(b), "l"(c)); return r;
}
__device__ __forceinline__ ull add2v(ull a, ull b) {
    ull r; asm("add.rn.f32x2 %0, %1, %2;" : "=l"(r) : "l"(a), "l"(b)); return r;
}
__device__ __forceinline__ ull mul2v(ull a, ull b) {
    ull r; asm("mul.rn.f32x2 %0, %1, %2;" : "=l"(r) : "l"(a), "l"(b)); return r;
}
__device__ __forceinline__ float2 up2(ull v) {
    float2 f; asm("mov.b64 {%0, %1}, %2;" : "=f"(f.x), "=f"(f.y) : "l"(v)); return f;
}
#define ABS2MASK 0x7FFFFFFF7FFFFFFFull

// ---------------- SGEMM body (R2/R4-proven): Y[M,128] = X[M,K] @ W[K,128] --
template <int K>
__device__ __forceinline__ void gemm_body(const float* __restrict__ X,
                                          const float* __restrict__ W,
                                          float* __restrict__ Y,
                                          int M, int bx) {
    __shared__ float Xs[16][128];   // transposed: Xs[k][row]
    __shared__ float Ws[16][128];

    int tid = threadIdx.x;
    int tx = tid & 15;      // cols tx*8 .. tx*8+7
    int ty = tid >> 4;      // rows ty*8 .. ty*8+7
    int rowBase = bx * 128;

    ull acc[8][4];
#pragma unroll
    for (int r = 0; r < 8; r++)
#pragma unroll
        for (int c = 0; c < 4; c++) acc[r][c] = 0ull;   // bit pattern == {0.f,0.f}

    for (int ks = 0; ks < K; ks += 16) {
        // load X tile transposed
#pragma unroll
        for (int it = 0; it < 2; it++) {
            int f = tid + it * 256;         // 0..511
            int row = f >> 2;               // 0..127
            int k4 = (f & 3) << 2;          // 0,4,8,12
            int gr = rowBase + row;
            float4 v = make_float4(0.f, 0.f, 0.f, 0.f);
            if (gr < M) v = *(const float4*)&X[(size_t)gr * K + ks + k4];
            Xs[k4 + 0][row] = v.x;
            Xs[k4 + 1][row] = v.y;
            Xs[k4 + 2][row] = v.z;
            Xs[k4 + 3][row] = v.w;
        }
        // load W tile
#pragma unroll
        for (int it = 0; it < 2; it++) {
            int f = tid + it * 256;
            int k = f >> 5;                 // 0..15
            int c = (f & 31) << 2;
            *(float4*)&Ws[k][c] = *(const float4*)&W[(size_t)(ks + k) * HID + c];
        }
        __syncthreads();

#pragma unroll
        for (int k = 0; k < 16; k++) {
            float4 xa = *(const float4*)&Xs[k][ty * 8];
            float4 xb = *(const float4*)&Xs[k][ty * 8 + 4];
            ulonglong2 wa = *(const ulonglong2*)&Ws[k][tx * 8];
            ulonglong2 wb = *(const ulonglong2*)&Ws[k][tx * 8 + 4];
            ull xp[8];
            xp[0] = pk2(xa.x); xp[1] = pk2(xa.y); xp[2] = pk2(xa.z); xp[3] = pk2(xa.w);
            xp[4] = pk2(xb.x); xp[5] = pk2(xb.y); xp[6] = pk2(xb.z); xp[7] = pk2(xb.w);
#pragma unroll
            for (int r = 0; r < 8; r++) {
                fma2(acc[r][0], xp[r], wa.x);
                fma2(acc[r][1], xp[r], wa.y);
                fma2(acc[r][2], xp[r], wb.x);
                fma2(acc[r][3], xp[r], wb.y);
            }
        }
        __syncthreads();
    }

#pragma unroll
    for (int r = 0; r < 8; r++) {
        int gr = rowBase + ty * 8 + r;
        if (gr < M) {
            float2 c0 = up2(acc[r][0]), c1 = up2(acc[r][1]);
            float2 c2 = up2(acc[r][2]), c3 = up2(acc[r][3]);
            float4 o0 = {c0.x, c0.y, c1.x, c1.y};
            float4 o1 = {c2.x, c2.y, c3.x, c3.y};
            *(float4*)&Y[(size_t)gr * HID + tx * 8]     = o0;
            *(float4*)&Y[(size_t)gr * HID + tx * 8 + 4] = o1;
        }
    }
}

// ---------------- fused: layer-1 dual GEMM + degree histogram --------------
__global__ void __launch_bounds__(256)
gemm1_hist_kernel(const float* __restrict__ X,
                  const float* __restrict__ WA, const float* __restrict__ WB,
                  float* __restrict__ YA, float* __restrict__ YB,
                  const int* __restrict__ ei, int M) {
    if (blockIdx.x < 2 * GEMM_NB) {
        int sel = blockIdx.x >= GEMM_NB;
        gemm_body<32>(X, sel ? WB : WA, sel ? YB : YA, M,
                      blockIdx.x - sel * GEMM_NB);
    } else {
        int e4 = (blockIdx.x - 2 * GEMM_NB) * 256 + threadIdx.x;
        if (e4 < EE / 4) {
            int4 d = ((const int4*)(ei + EE))[e4];
            atomicAdd(&g_deg[d.x], 1);
            atomicAdd(&g_deg[d.y], 1);
            atomicAdd(&g_deg[d.z], 1);
            atomicAdd(&g_deg[d.w], 1);
        }
    }
}

__global__ void __launch_bounds__(256)
gemm_dual_kernel(const float* __restrict__ X,
                 const float* __restrict__ WA, const float* __restrict__ WB,
                 float* __restrict__ YA, float* __restrict__ YB, int M) {
    gemm_body<128>(X, blockIdx.y ? WB : WA, blockIdx.y ? YB : YA, M, blockIdx.x);
}

// ---------------- CSR scan + scatter (R4-proven multi-block) ----------------
__global__ void scan1_kernel() {
    __shared__ int sh[1024];
    int t = threadIdx.x;
    int base = blockIdx.x * 4096 + t * 4;
    // +1 = implicit self loop per node
    int v0 = (base + 0 < NN) ? g_deg[base + 0] + 1 : 0;
    int v1 = (base + 1 < NN) ? g_deg[base + 1] + 1 : 0;
    int v2 = (base + 2 < NN) ? g_deg[base + 2] + 1 : 0;
    int v3 = (base + 3 < NN) ? g_deg[base + 3] + 1 : 0;
    int p0 = v0, p1 = p0 + v1, p2 = p1 + v2, p3 = p2 + v3;
    sh[t] = p3;
    __syncthreads();
    for (int off = 1; off < 1024; off <<= 1) {
        int add = (t >= off) ? sh[t - off] : 0;
        __syncthreads();
        sh[t] += add;
        __syncthreads();
    }
    int excl = sh[t] - p3;
    if (base + 0 < NN) g_rowptr[base + 0] = excl;
    if (base + 1 < NN) g_rowptr[base + 1] = excl + p0;
    if (base + 2 < NN) g_rowptr[base + 2] = excl + p1;
    if (base + 3 < NN) g_rowptr[base + 3] = excl + p2;
    if (t == 1023) g_blocksums[blockIdx.x] = sh[1023];  // raw block totals
}

__global__ void scan3_kernel() {
    int i = blockIdx.x * blockDim.x + threadIdx.x;
    if (i < NN) {
        int idx = i >> 12;
        int off = 0;
        for (int b = 0; b < idx; b++) off += g_blocksums[b];
        int r = g_rowptr[i] + off;
        g_rowptr[i] = r;
        g_cursor[i] = r;
        g_deg[i] = 0;               // restore for next graph replay
    } else if (i == NN) {
        g_rowptr[NN] = ET;
    }
}

__global__ void scatter_kernel(const int* __restrict__ ei) {
    int i = blockIdx.x * blockDim.x + threadIdx.x;
    if (i >= ET) return;
    int s, d;
    if (i < EE) { s = ei[i]; d = ei[EE + i]; }
    else        { s = i - EE; d = s; }
    int p = atomicAdd(&g_cursor[d], 1);
    g_src[p] = s;
}

// ---------------- GATv2 aggregation core (R7-proven) ------------------------
// packed f32x2 math + unroll-4 reload-in-place pipeline.
// Logits tiny (weights ~0.05) -> exp without max-shift is safe.
// leaky_relu(t) = 0.6t + 0.4|t| for slope 0.2.
__device__ __forceinline__ float4 agg_core(int node, int lane,
                                           const float* __restrict__ xl,
                                           const float* __restrict__ xr,
                                           const float* __restrict__ att) {
    float4 xr4 = *(const float4*)&xr[(size_t)node * HID + lane * 4];
    float4 a4  = *(const float4*)&att[lane * 4];
    const float c6 = 0.5f * (1.f + SLOPE), c4 = 0.5f * (1.f - SLOPE);
    ull xrA = mk2(xr4.x, xr4.y), xrB = mk2(xr4.z, xr4.w);
    ull a06A = mk2(a4.x * c6, a4.y * c6), a06B = mk2(a4.z * c6, a4.w * c6);
    ull a04A = mk2(a4.x * c4, a4.y * c4), a04B = mk2(a4.z * c4, a4.w * c4);

    int e0 = g_rowptr[node], e1 = g_rowptr[node + 1];

    ull accA = 0ull, accB = 0ull;      // bit pattern == {0.f,0.f}
    float denom = 0.f;

#define LOADE(k, dA, dB) {                                                    \
        int _s = __shfl_sync(0xffffffffu, sReg, (k));                         \
        ulonglong2 _v = *(const ulonglong2*)&xl[(size_t)_s * HID + lane * 4]; \
        dA = _v.x; dB = _v.y; }

#define PROCE(cA, cB) {                                                       \
        ull t01 = add2v(cA, xrA), t23 = add2v(cB, xrB);                       \
        ull v2 = mul2v(t01, a06A);                                            \
        v2 = fma2v(t01 & ABS2MASK, a04A, v2);                                 \
        v2 = fma2v(t23, a06B, v2);                                            \
        v2 = fma2v(t23 & ABS2MASK, a04B, v2);                                 \
        float2 vv = up2(v2);                                                  \
        float v = vv.x + vv.y;                                                \
        v += __shfl_xor_sync(0xffffffffu, v, 1);                              \
        v += __shfl_xor_sync(0xffffffffu, v, 2);                              \
        v += __shfl_xor_sync(0xffffffffu, v, 4);                              \
        float e = __expf(v);                                                  \
        denom += e;                                                           \
        ull ep = pk2(e);                                                      \
        fma2(accA, ep, cA);                                                   \
        fma2(accB, ep, cB); }

    for (int eb = e0; eb < e1; eb += 32) {
        int cnt = min(32, e1 - eb);
        // invalid lanes get node 0 (safe to load, never processed)
        int sReg = (lane < cnt) ? g_src[eb + lane] : 0;

        ull c0a, c0b, c1a, c1b, c2a, c2b, c3a, c3b;
        LOADE(0, c0a, c0b);
        LOADE(1, c1a, c1b);
        LOADE(2, c2a, c2b);
        LOADE(3, c3a, c3b);

        int j = 0;
        for (; j + 4 <= cnt; j += 4) {
            PROCE(c0a, c0b); LOADE(j + 4, c0a, c0b);
            PROCE(c1a, c1b); LOADE(j + 5, c1a, c1b);
            PROCE(c2a, c2b); LOADE(j + 6, c2a, c2b);
            PROCE(c3a, c3b); LOADE(j + 7, c3a, c3b);
        }
        int rem = cnt - j;           // 0..3, warp-uniform
        if (rem > 0) { PROCE(c0a, c0b); }
        if (rem > 1) { PROCE(c1a, c1b); }
        if (rem > 2) { PROCE(c2a, c2b); }
    }
#undef LOADE
#undef PROCE

    float inv = 1.f / denom;
    float2 rA = up2(accA), rB = up2(accB);
    float4 res;
    res.x = rA.x * inv; res.y = rA.y * inv;
    res.z = rB.x * inv; res.w = rB.y * inv;
    return res;
}

__device__ __forceinline__ float4 ln_epi(float4 r, int lane,
                                         const float* __restrict__ bias,
                                         const float* __restrict__ gamma,
                                         const float* __restrict__ beta) {
    float4 b4 = *(const float4*)&bias[lane * 4];
    r.x += b4.x; r.y += b4.y; r.z += b4.z; r.w += b4.w;
    float s1 = r.x + r.y + r.z + r.w;
    float s2 = r.x * r.x + r.y * r.y + r.z * r.z + r.w * r.w;
#pragma unroll
    for (int off = 16; off > 0; off >>= 1) {
        s1 += __shfl_xor_sync(0xffffffffu, s1, off);
        s2 += __shfl_xor_sync(0xffffffffu, s2, off);
    }
    float mean = s1 * (1.f / 128.f);
    float var  = s2 * (1.f / 128.f) - mean * mean;
    float rstd = rsqrtf(var + LN_EPS);
    float4 g4 = *(const float4*)&gamma[lane * 4];
    float4 bb4 = *(const float4*)&beta[lane * 4];
    r.x = (r.x - mean) * rstd * g4.x + bb4.x;
    r.y = (r.y - mean) * rstd * g4.y + bb4.y;
    r.z = (r.z - mean) * rstd * g4.z + bb4.z;
    r.w = (r.w - mean) * rstd * g4.w + bb4.w;
    return r;
}

// ---------------- layer 1: agg + bias + LN + ELU -> h1 ---------------------
__global__ void __launch_bounds__(256)
gat_layer1_kernel(const float* __restrict__ xl, const float* __restrict__ xr,
                  const float* __restrict__ att, const float* __restrict__ bias,
                  const float* __restrict__ gamma, const float* __restrict__ beta,
                  float* __restrict__ out, int Nn) {
    int warp = (blockIdx.x * blockDim.x + threadIdx.x) >> 5;
    if (warp >= Nn) return;
    int lane = threadIdx.x & 31;
    float4 r = agg_core(warp, lane, xl, xr, att);
    r = ln_epi(r, lane, bias, gamma, beta);
    r.x = r.x > 0.f ? r.x : expm1f(r.x);
    r.y = r.y > 0.f ? r.y : expm1f(r.y);
    r.z = r.z > 0.f ? r.z : expm1f(r.z);
    r.w = r.w > 0.f ? r.w : expm1f(r.w);
    *(float4*)&out[(size_t)warp * HID + lane * 4] = r;
}

// ---------------- layer 2: agg + bias + LN + residual + ELU -> h2 ----------
__global__ void __launch_bounds__(256)
gat_layer2_kernel(const float* __restrict__ xl, const float* __restrict__ xr,
                  const float* __restrict__ att, const float* __restrict__ bias,
                  const float* __restrict__ gamma, const float* __restrict__ beta,
                  const float* __restrict__ resid, float* __restrict__ out, int Nn) {
    int warp = (blockIdx.x * blockDim.x + threadIdx.x) >> 5;
    if (warp >= Nn) return;
    int lane = threadIdx.x & 31;
    float4 r = agg_core(warp, lane, xl, xr, att);
    r = ln_epi(r, lane, bias, gamma, beta);
    float4 rs = *(const float4*)&resid[(size_t)warp * HID + lane * 4];
    r.x += rs.x; r.y += rs.y; r.z += rs.z; r.w += rs.w;
    r.x = r.x > 0.f ? r.x : expm1f(r.x);
    r.y = r.y > 0.f ? r.y : expm1f(r.y);
    r.z = r.z > 0.f ? r.z : expm1f(r.z);
    r.w = r.w > 0.f ? r.w : expm1f(r.w);
    *(float4*)&out[(size_t)warp * HID + lane * 4] = r;
}

// ---------------- heads: GEMM-style fused MLP heads ------------------------
// Block = 192 threads, 64 nodes. Stage1: [64x128] @ [128x96] (Wp1|Wu1) with
// FFMA2, thread micro-tile 4 rows x 8 cols. Stage2: 6-col output layers +
// softplus, one thread per node per head.
__global__ void __launch_bounds__(192)
heads_kernel(const float* __restrict__ h,
             const float* __restrict__ Wp1, const float* __restrict__ bp1,
             const float* __restrict__ Wp2, const float* __restrict__ bp2,
             const float* __restrict__ Wu1, const float* __restrict__ bu1,
             const float* __restrict__ Wu2, const float* __restrict__ bu2,
             float* __restrict__ out, int Nn) {
    __shared__ float hs[64][132];      // padded row-major h tile (33KB)
    __shared__ float wp2s[64 * 6];
    __shared__ float wu2s[32 * 6];

    int tid = threadIdx.x;
    int tx = tid % 12;        // 12 col-groups of 8 (96 = 64 pred + 32 unc)
    int ty = tid / 12;        // 16 row-groups of 4
    int base = blockIdx.x * 64;

    // stage small stage-2 weights
    for (int i = tid; i < 64 * 6; i += 192) wp2s[i] = Wp2[i];
    for (int i = tid; i < 32 * 6; i += 192) wu2s[i] = Wu2[i];

    // stage h tile (coalesced loads, conflict-free float4 STS)
    for (int i = tid; i < 64 * 32; i += 192) {
        int row = i >> 5;
        int c4 = (i & 31) << 2;
        int g = base + row;
        float4 v = make_float4(0.f, 0.f, 0.f, 0.f);
        if (g < Nn) v = *(const float4*)&h[(size_t)g * HID + c4];
        *(float4*)&hs[row][c4] = v;
    }
    __syncthreads();

    // stage 1: hidden layers with FFMA2
    const float* wbase;
    int wstr;
    if (tx < 8) { wbase = Wp1 + tx * 8; wstr = 64; }
    else        { wbase = Wu1 + (tx - 8) * 8; wstr = 32; }
    ull bz[4];
#pragma unroll
    for (int c = 0; c < 4; c++) {
        float blo = (tx < 8) ? bp1[tx * 8 + 2 * c]     : bu1[(tx - 8) * 8 + 2 * c];
        float bhi = (tx < 8) ? bp1[tx * 8 + 2 * c + 1] : bu1[(tx - 8) * 8 + 2 * c + 1];
        bz[c] = mk2(blo, bhi);
    }

    ull acc[4][4];
#pragma unroll
    for (int r = 0; r < 4; r++)
#pragma unroll
        for (int c = 0; c < 4; c++) acc[r][c] = 0ull;

    int r0 = ty * 4;
#pragma unroll 4
    for (int k = 0; k < 128; k++) {
        ull x0 = pk2(hs[r0 + 0][k]);
        ull x1 = pk2(hs[r0 + 1][k]);
        ull x2 = pk2(hs[r0 + 2][k]);
        ull x3 = pk2(hs[r0 + 3][k]);
        ulonglong2 w01 = *(const ulonglong2*)(wbase + (size_t)k * wstr);
        ulonglong2 w23 = *(const ulonglong2*)(wbase + (size_t)k * wstr + 4);
        fma2(acc[0][0], x0, w01.x); fma2(acc[0][1], x0, w01.y);
        fma2(acc[0][2], x0, w23.x); fma2(acc[0][3], x0, w23.y);
        fma2(acc[1][0], x1, w01.x); fma2(acc[1][1], x1, w01.y);
        fma2(acc[1][2], x1, w23.x); fma2(acc[1][3], x1, w23.y);
        fma2(acc[2][0], x2, w01.x); fma2(acc[2][1], x2, w01.y);
        fma2(acc[2][2], x2, w23.x); fma2(acc[2][3], x2, w23.y);
        fma2(acc[3][0], x3, w01.x); fma2(acc[3][1], x3, w01.y);
        fma2(acc[3][2], x3, w23.x); fma2(acc[3][3], x3, w23.y);
    }
    __syncthreads();   // done reading hs; safe to overlay ph/uh

    // overlay ph[64][65], uh[64][33] onto the hs region (padded: conflict-free)
    float* ph = &hs[0][0];
    float* uh = ph + 64 * 65;

#pragma unroll
    for (int r = 0; r < 4; r++) {
        int row = r0 + r;
#pragma unroll
        for (int c = 0; c < 4; c++) {
            float2 v = up2(add2v(acc[r][c], bz[c]));
            v.x = fmaxf(v.x, 0.f);
            v.y = fmaxf(v.y, 0.f);
            if (tx < 8) {
                ph[row * 65 + tx * 8 + 2 * c]     = v.x;
                ph[row * 65 + tx * 8 + 2 * c + 1] = v.y;
            } else {
                uh[row * 33 + (tx - 8) * 8 + 2 * c]     = v.x;
                uh[row * 33 + (tx - 8) * 8 + 2 * c + 1] = v.y;
            }
        }
    }
    __syncthreads();

    // stage 2
    if (tid < 64) {
        // prediction head: node = tid
        int g = base + tid;
        if (g < Nn) {
            ull a0 = mk2(bp2[0], bp2[1]);
            ull a1 = mk2(bp2[2], bp2[3]);
            ull a2 = mk2(bp2[4], bp2[5]);
#pragma unroll 4
            for (int k = 0; k < 64; k++) {
                ull p = pk2(ph[tid * 65 + k]);
                ull w0 = *(const ull*)&wp2s[k * 6];
                ull w1 = *(const ull*)&wp2s[k * 6 + 2];
                ull w2 = *(const ull*)&wp2s[k * 6 + 4];
                fma2(a0, p, w0);
                fma2(a1, p, w1);
                fma2(a2, p, w2);
            }
            float2 o0 = up2(a0), o1 = up2(a1), o2 = up2(a2);
            float* op = &out[(size_t)g * 6];
            op[0] = o0.x; op[1] = o0.y; op[2] = o1.x;
            op[3] = o1.y; op[4] = o2.x; op[5] = o2.y;
        }
    } else if (tid < 128) {
        // uncertainty head: node = tid - 64
        int n = tid - 64;
        int g = base + n;
        if (g < Nn) {
            ull a0 = mk2(bu2[0], bu2[1]);
            ull a1 = mk2(bu2[2], bu2[3]);
            ull a2 = mk2(bu2[4], bu2[5]);
#pragma unroll 4
            for (int k = 0; k < 32; k++) {
                ull p = pk2(uh[n * 33 + k]);
                ull w0 = *(const ull*)&wu2s[k * 6];
                ull w1 = *(const ull*)&wu2s[k * 6 + 2];
                ull w2 = *(const ull*)&wu2s[k * 6 + 4];
                fma2(a0, p, w0);
                fma2(a1, p, w1);
                fma2(a2, p, w2);
            }
            float q[6];
            float2 o0 = up2(a0), o1 = up2(a1), o2 = up2(a2);
            q[0] = o0.x; q[1] = o0.y; q[2] = o1.x;
            q[3] = o1.y; q[4] = o2.x; q[5] = o2.y;
            float* op = &out[(size_t)Nn * 6 + (size_t)g * 6];
#pragma unroll
            for (int c = 0; c < 6; c++)
                op[c] = fmaxf(q[c], 0.f) + log1pf(__expf(-fabsf(q[c])));
        }
    }
}

// ---------------- launcher -------------------------------------------------
extern "C" void kernel_launch(void* const* d_in, const int* in_sizes, int n_in,
                              void* d_out, int out_size) {
    const float* x     = (const float*)d_in[0];
    const int*   ei    = (const int*)d_in[1];
    const float* Wl1   = (const float*)d_in[2];
    const float* Wr1   = (const float*)d_in[3];
    const float* att1  = (const float*)d_in[4];
    const float* bias1 = (const float*)d_in[5];
    const float* g1    = (const float*)d_in[6];
    const float* b1    = (const float*)d_in[7];
    const float* Wl2   = (const float*)d_in[8];
    const float* Wr2   = (const float*)d_in[9];
    const float* att2  = (const float*)d_in[10];
    const float* bias2 = (const float*)d_in[11];
    const float* g2    = (const float*)d_in[12];
    const float* b2    = (const float*)d_in[13];
    const float* Wp1   = (const float*)d_in[14];
    const float* bp1   = (const float*)d_in[15];
    const float* Wp2   = (const float*)d_in[16];
    const float* bp2   = (const float*)d_in[17];
    const float* Wu1   = (const float*)d_in[18];
    const float* bu1   = (const float*)d_in[19];
    const float* Wu2   = (const float*)d_in[20];
    const float* bu2   = (const float*)d_in[21];
    float* out = (float*)d_out;

    float *xl, *xr, *h1, *h2;
    cudaGetSymbolAddress((void**)&xl, g_xl);
    cudaGetSymbolAddress((void**)&xr, g_xr);
    cudaGetSymbolAddress((void**)&h1, g_h1);
    cudaGetSymbolAddress((void**)&h2, g_h2);

    // fused: layer-1 dual GEMM + degree histogram
    int histBlocks = (EE / 4 + 255) / 256;
    gemm1_hist_kernel<<<2 * GEMM_NB + histBlocks, 256>>>(x, Wl1, Wr1, xl, xr, ei, NN);

    // CSR scan + scatter
    scan1_kernel<<<SCAN_NB, 1024>>>();
    scan3_kernel<<<(NN + 256) / 256, 256>>>();
    scatter_kernel<<<(ET + 255) / 256, 256>>>(ei);

    // layer 1 aggregation
    gat_layer1_kernel<<<(NN + 7) / 8, 256>>>(xl, xr, att1, bias1, g1, b1, h1, NN);

    // layer 2 dual GEMM
    dim3 ggrid(GEMM_NB, 2);
    gemm_dual_kernel<<<ggrid, 256>>>(h1, Wl2, Wr2, xl, xr, NN);

    // layer 2 aggregation -> h2
    gat_layer2_kernel<<<(NN + 7) / 8, 256>>>(
        xl, xr, att2, bias2, g2, b2, h1, h2, NN);

    // MLP heads (GEMM-style)
    heads_kernel<<<HEADS_NB, 192>>>(h2, Wp1, bp1, Wp2, bp2,
                                    Wu1, bu1, Wu2, bu2, out, NN);
}